// round 16
// baseline (speedup 1.0000x reference)
#include <cuda_runtime.h>
#include <math.h>

#define N_POINTS 128
#define STEPS    50
#define N_EVENTS 10000
#define DT       2.0f
#define SQRT_PI_F 1.7724539f
#define PAD_S    52                                       // padded step stride
#define N_GROUPS 25                                       // 25 groups of 2 steps = 50 exact

#define N_PAIRS      ((N_POINTS * (N_POINTS - 1)) / 2)    // 8128
#define PAIR_THREADS (N_PAIRS * N_GROUPS)                 // 203200
#define MAIN_THREADS 512
#define MAIN_BLOCKS  ((PAIR_THREADS + N_EVENTS + MAIN_THREADS - 1) / MAIN_THREADS)  // 417
#define ACC_SLOTS    32

// ---- device scratch (allocation-free contract) ----
__device__ __align__(16) float4 g_T[N_POINTS * PAD_S];    // (Zx, Zy, Vx, Vy) per (point, step)
__device__ __align__(16) float2 g_tstf[PAD_S];            // (ts', tf'); tf'==ts' when invalid
__device__ double        g_accs[ACC_SLOTS];               // sharded partial sums
__device__ unsigned int  g_count = 0;

__device__ __forceinline__ int tri_base(int i) {          // # pairs before row i
    return i * (N_POINTS - 1) - (i * (i - 1)) / 2;
}

// Abramowitz-Stegun 7.1.28: erf(x) = 1 - (1 + a1 x + ... + a6 x^6)^-16,
// |err| <= 3e-7. No exp; single MUFU reciprocal. Overflow-safe.
__device__ __forceinline__ float fast_erf28(float x) {
    const float a1 = 0.0705230784f, a2 = 0.0422820123f, a3 = 0.0092705272f,
                a4 = 0.0001520143f, a5 = 0.0002765672f, a6 = 0.0000430638f;
    float ax = fabsf(x);
    float p = fmaf(ax, a6, a5);
    p = fmaf(ax, p, a4);
    p = fmaf(ax, p, a3);
    p = fmaf(ax, p, a2);
    p = fmaf(ax, p, a1);
    p = fmaf(ax, p, 1.0f);
    float p2  = p  * p;
    float p4  = p2 * p2;
    float p8  = p4 * p4;
    float p16 = p8 * p8;
    float r   = __fdividef(1.0f, p16);                    // MUFU.RCP + FMUL
    return copysignf(1.0f - r, x);
}

// ---------------------------------------------------------------------------
// Kernel A: 2 independent blocks x 1024.
//   b0: event-time boundary scan -> ts/tf table
//   b1: interleaved (Z,V) float4 table (cumsum + copy in one pass)
// ---------------------------------------------------------------------------
__global__ void __launch_bounds__(1024)
prep_kernel(const float* __restrict__ data,
            const float* __restrict__ z0,
            const float* __restrict__ v0) {
    const int tid = threadIdx.x;

    if (blockIdx.x == 0) {
        __shared__ float sTs[STEPS + 1];
        __shared__ float sVl[STEPS];
        const float denom = DT + DT * 0.001f;             // 2.002f, matches ref rounding
        const float tlast = __ldg(&data[(N_EVENTS - 1) * 3 + 2]);
        if (tid <= STEPS) {
            sTs[tid] = tlast;                             // empty segment -> times[M-1]
            if (tid < STEPS) sVl[tid] = 0.0f;
        }
        __syncthreads();
        for (int m = tid; m < N_EVENTS; m += 1024) {      // 10 iters, independent loads
            float t   = data[m * 3 + 2];
            int   idx = (int)floorf(t / denom);
            int newseg = (m == 0) ||
                         (((int)floorf(data[m * 3 - 1] / denom)) != idx);
            if (newseg) { sTs[idx] = t; sVl[idx] = 1.0f; }
        }
        __syncthreads();
        if (tid < STEPS) {
            float tsA = sTs[tid];
            float tfA = (sVl[tid] != 0.0f) ? sTs[tid + 1] : tsA;  // invalid -> term 0
            g_tstf[tid] = make_float2(tsA, tfA);
        } else if (tid < PAD_S) {
            g_tstf[tid] = make_float2(0.0f, 0.0f);
        }
    } else {
        if (tid < N_POINTS) {                             // one point per thread
            const float* vx = v0 + (2 * tid)     * STEPS;
            const float* vy = v0 + (2 * tid + 1) * STEPS;
            float zx = __ldg(&z0[2 * tid]);
            float zy = __ldg(&z0[2 * tid + 1]);
            float4* Tr = g_T + tid * PAD_S;
            Tr[0] = make_float4(zx, zy, vx[0], vy[0]);    // Z_steps[0] = z0
            float cumx = 0.0f, cumy = 0.0f;
            #pragma unroll
            for (int s = 1; s < STEPS; ++s) {
                cumx += zx + vx[s - 1] * DT;              // same fp order as reference
                cumy += zy + vy[s - 1] * DT;
                Tr[s] = make_float4(cumx, cumy, vx[s], vy[s]);
            }
            Tr[50] = make_float4(0.f, 0.f, 0.f, 0.f);     // pads
            Tr[51] = make_float4(0.f, 0.f, 0.f, 0.f);
        }
    }
#if __CUDA_ARCH__ >= 900
    cudaTriggerProgrammaticLaunchCompletion();
#endif
}

// ---------------------------------------------------------------------------
// Kernel B: one (pair, 2-step group) per thread; indices decoded BEFORE the
// PDL sync; 6 loads/pair-thread; sharded accumulator.
// ---------------------------------------------------------------------------
union F4 { float4 v; float a[4]; };

__global__ void __launch_bounds__(MAIN_THREADS)
main_kernel(const float* __restrict__ data,
            const float* __restrict__ beta,
            float* __restrict__ out) {
    const int   gid = blockIdx.x * MAIN_THREADS + threadIdx.x;
    const float b0  = __ldg(&beta[0]);

    // ---- pre-sync phase: everything that does NOT depend on prep tables ----
    int  oi = 0, oj = 0, s0 = 0;
    bool is_pair = false, is_event = false;
    float ev_delta = 0.0f;
    if (gid < PAIR_THREADS) {
        is_pair = true;
        int p = gid / N_GROUPS;
        s0 = (gid - p * N_GROUPS) * 2;
        float disc = (float)(255 * 255 - 8 * p);          // triangular decode + fixup
        int i = (int)((255.0f - sqrtf(disc)) * 0.5f);
        i = min(max(i, 0), N_POINTS - 2);
        while (i < N_POINTS - 2 && tri_base(i + 1) <= p) ++i;
        while (i > 0 && tri_base(i) > p) --i;
        int j = i + 1 + (p - tri_base(i));
        oi = i * PAD_S + s0;
        oj = j * PAD_S + s0;
    } else if (gid - PAIR_THREADS < N_EVENTS) {
        is_event = true;
        int e = gid - PAIR_THREADS;
        const float denom = DT + DT * 0.001f;
        float si = __ldg(&data[e * 3]);                   // harness input, prep-independent
        float dj = __ldg(&data[e * 3 + 1]);
        float t  = __ldg(&data[e * 3 + 2]);
        float stepf = floorf(t / denom);
        int   id    = (int)stepf;
        ev_delta = t - stepf * DT;
        oi = (int)si * PAD_S + id;
        oj = (int)dj * PAD_S + id;
    }

#if __CUDA_ARCH__ >= 900
    cudaGridDependencySynchronize();                      // tables ready past here
#endif

    float facc = 0.0f;
    if (is_pair) {
        float4 ti0 = __ldg(&g_T[oi]);
        float4 ti1 = __ldg(&g_T[oi + 1]);
        float4 tj0 = __ldg(&g_T[oj]);
        float4 tj1 = __ldg(&g_T[oj + 1]);
        F4 tt; tt.v = __ldg((const float4*)(&g_tstf[s0]));    // (ts0,tf0,ts1,tf1)

        #pragma unroll
        for (int k = 0; k < 2; ++k) {
            float4 ti = k ? ti1 : ti0;
            float4 tj = k ? tj1 : tj0;
            float dzx = ti.x - tj.x;
            float dzy = ti.y - tj.y;
            float dvx = ti.z - tj.z;
            float dvy = ti.w - tj.w;

            float a  = fmaxf(dvx * dvx + dvy * dvy, 1e-10f);
            float b  = 2.0f * (dzx * dvx + dzy * dvy);
            float c  = dzx * dzx + dzy * dzy;
            float bc = b0 - c;
            float ts = tt.a[2 * k];
            float tf = tt.a[2 * k + 1];

            // MUFU-free skip tests (exact algebra, see R11)
            float u = fmaf(2.0f * a, ts, b);
            float v = fmaf(2.0f * a, tf, b);
            bool live = (fmaf(4.0f * a, bc + 25.0f, b * b) > 0.0f)
                     && (u <= 0.0f || u * u < 100.0f * a)
                     && (v >= 0.0f || v * v < 100.0f * a);
            if (live) {
                float rsa    = rsqrtf(a);
                float inv2sa = 0.5f * rsa;
                float sa     = a * rsa;
                float shift  = b * inv2sa;
                float arg    = bc + shift * shift;
                float loa    = fmaf(sa, ts, shift);
                float hia    = fmaf(sa, tf, shift);
                float pref   = SQRT_PI_F * inv2sa * __expf(arg);
                facc -= pref * (fast_erf28(hia) - fast_erf28(loa));
            }
        }
    } else if (is_event) {
        float4 ti = __ldg(&g_T[oi]);
        float4 tj = __ldg(&g_T[oj]);
        float dx = (ti.x + ti.z * ev_delta) - (tj.x + tj.z * ev_delta);
        float dy = (ti.y + ti.w * ev_delta) - (tj.y + tj.w * ev_delta);
        facc += b0 - (dx * dx + dy * dy);
    }

    // ---- reduction: FLOAT warp shuffle -> double smem -> warp0 -> sharded atomic ----
    __shared__ double sRd[MAIN_THREADS / 32];
    float fv = facc;
    #pragma unroll
    for (int off = 16; off > 0; off >>= 1)                // FP32 pipe
        fv += __shfl_down_sync(0xffffffffu, fv, off);
    int warp = threadIdx.x >> 5, lane = threadIdx.x & 31;
    if (lane == 0) sRd[warp] = (double)fv;                // promote once per warp
    __syncthreads();
    if (warp == 0) {
        double v = (lane < MAIN_THREADS / 32) ? sRd[lane] : 0.0;
        #pragma unroll
        for (int off = 8; off > 0; off >>= 1)             // 16 warps -> 4 DADD levels
            v += __shfl_down_sync(0xffffffffu, v, off);
        if (lane == 0) {
            atomicAdd(&g_accs[blockIdx.x & (ACC_SLOTS - 1)], v);  // sharded: ~13/slot
            __threadfence();
            unsigned int old = atomicAdd(&g_count, 1u);
            if (old == gridDim.x - 1) {                   // last block: gather + reset
                double total = 0.0;
                #pragma unroll
                for (int s = 0; s < ACC_SLOTS; ++s) {     // independent loads, MLP-hidden
                    total += atomicAdd(&g_accs[s], 0.0);
                }
                out[0] = (float)total;
                #pragma unroll
                for (int s = 0; s < ACC_SLOTS; ++s) g_accs[s] = 0.0;
                g_count = 0u;                             // reset for next graph replay
            }
        }
    }
}

// Inputs (metadata order): data[30000], t0[1], tn[1], beta[1], z0[256], v0[12800]
extern "C" void kernel_launch(void* const* d_in, const int* in_sizes, int n_in,
                              void* d_out, int out_size) {
    const float* data = (const float*)d_in[0];
    const float* beta = (const float*)d_in[3];
    const float* z0   = (const float*)d_in[4];
    const float* v0   = (const float*)d_in[5];
    float* out = (float*)d_out;

    prep_kernel<<<2, 1024>>>(data, z0, v0);

    // PDL: overlap main's launch + pre-sync index phase with prep's execution
    cudaLaunchConfig_t cfg = {};
    cfg.gridDim  = dim3(MAIN_BLOCKS, 1, 1);
    cfg.blockDim = dim3(MAIN_THREADS, 1, 1);
    cfg.stream   = 0;
    cudaLaunchAttribute attr[1];
    attr[0].id = cudaLaunchAttributeProgrammaticStreamSerialization;
    attr[0].val.programmaticStreamSerializationAllowed = 1;
    cfg.attrs    = attr;
    cfg.numAttrs = 1;
    cudaLaunchKernelEx(&cfg, main_kernel, data, beta, out);
}

// round 17
// speedup vs baseline: 1.3792x; 1.3792x over previous
#include <cuda_runtime.h>
#include <math.h>

#define N_POINTS 128
#define STEPS    50
#define N_EVENTS 10000
#define DT       2.0f
#define SQRT_PI_F 1.7724539f
#define PAD_S    52                                       // padded step stride
#define N_GROUPS 25                                       // 25 groups of 2 steps = 50 exact

#define N_PAIRS      ((N_POINTS * (N_POINTS - 1)) / 2)    // 8128
#define PAIR_THREADS (N_PAIRS * N_GROUPS)                 // 203200
#define MAIN_THREADS 256
#define MAIN_BLOCKS  ((PAIR_THREADS + N_EVENTS + MAIN_THREADS - 1) / MAIN_THREADS)  // 833

// ---- device scratch (allocation-free contract) ----
__device__ __align__(16) float  g_Zx[N_POINTS * PAD_S];
__device__ __align__(16) float  g_Zy[N_POINTS * PAD_S];
__device__ __align__(16) float  g_Vx[N_POINTS * PAD_S];
__device__ __align__(16) float  g_Vy[N_POINTS * PAD_S];
__device__ __align__(16) float2 g_tstf[PAD_S];            // (ts', tf'); tf'==ts' when invalid
__device__ unsigned char g_rowi[N_PAIRS];                 // pair -> row i LUT
__device__ double        g_acc   = 0.0;
__device__ unsigned int  g_count = 0;

__device__ __forceinline__ int tri_base(int i) {          // # pairs before row i
    return i * (N_POINTS - 1) - (i * (i - 1)) / 2;
}

// Abramowitz-Stegun 7.1.28: erf(x) = 1 - (1 + a1 x + ... + a6 x^6)^-16,
// |err| <= 3e-7. NO exp — single MUFU reciprocal via __fdividef.
// Overflow-safe: p^16 -> inf  =>  1/inf -> 0  =>  erf -> 1.
__device__ __forceinline__ float fast_erf28(float x) {
    const float a1 = 0.0705230784f, a2 = 0.0422820123f, a3 = 0.0092705272f,
                a4 = 0.0001520143f, a5 = 0.0002765672f, a6 = 0.0000430638f;
    float ax = fabsf(x);
    float p = fmaf(ax, a6, a5);
    p = fmaf(ax, p, a4);
    p = fmaf(ax, p, a3);
    p = fmaf(ax, p, a2);
    p = fmaf(ax, p, a1);
    p = fmaf(ax, p, 1.0f);
    float p2  = p  * p;
    float p4  = p2 * p2;
    float p8  = p4 * p4;
    float p16 = p8 * p8;
    float r   = __fdividef(1.0f, p16);                    // MUFU.RCP + FMUL
    return copysignf(1.0f - r, x);
}

// ---------------------------------------------------------------------------
// Kernel A: 4 independent blocks x 1024 — each latency chain on its own SM.
//   b0: event-time boundary scan -> ts/tf table
//   b1: Z cumsum (+pads)   b2: V copy   b3: pair-row LUT
// ---------------------------------------------------------------------------
__global__ void __launch_bounds__(1024)
prep_kernel(const float* __restrict__ data,
            const float* __restrict__ z0,
            const float* __restrict__ v0) {
    const int tid = threadIdx.x;
    const int blk = blockIdx.x;

    if (blk == 0) {
        __shared__ float sTs[STEPS + 1];
        __shared__ float sVl[STEPS];
        const float denom = DT + DT * 0.001f;             // 2.002f, matches ref rounding
        const float tlast = __ldg(&data[(N_EVENTS - 1) * 3 + 2]);
        if (tid <= STEPS) {
            sTs[tid] = tlast;                             // empty segment -> times[M-1]
            if (tid < STEPS) sVl[tid] = 0.0f;
        }
        __syncthreads();
        for (int m = tid; m < N_EVENTS; m += 1024) {      // 10 iters, independent loads
            float t   = data[m * 3 + 2];
            int   idx = (int)floorf(t / denom);
            int newseg = (m == 0) ||
                         (((int)floorf(data[m * 3 - 1] / denom)) != idx);
            if (newseg) { sTs[idx] = t; sVl[idx] = 1.0f; }
        }
        __syncthreads();
        if (tid < STEPS) {
            float tsA = sTs[tid];
            float tfA = (sVl[tid] != 0.0f) ? sTs[tid + 1] : tsA;  // invalid -> term 0
            g_tstf[tid] = make_float2(tsA, tfA);
        } else if (tid < PAD_S) {
            g_tstf[tid] = make_float2(0.0f, 0.0f);
        }
    } else if (blk == 1) {
        if (tid < 2 * N_POINTS) {                         // Z cumsum, one row/thread
            int p = tid >> 1, d = tid & 1;
            float* Zr = (d ? g_Zy : g_Zx) + p * PAD_S;
            float* Vr = (d ? g_Vy : g_Vx) + p * PAD_S;
            const float* vr = v0 + tid * STEPS;           // v0 row = p*2 + d
            float z = __ldg(&z0[tid]);
            Zr[0] = z;                                    // Z_steps[0] = z0
            float cum = 0.0f;
            #pragma unroll
            for (int s = 1; s < STEPS; ++s) {
                cum += z + vr[s - 1] * DT;                // same fp order as reference
                Zr[s] = cum;
            }
            Zr[50] = 0.0f; Zr[51] = 0.0f;
            Vr[50] = 0.0f; Vr[51] = 0.0f;
        }
    } else if (blk == 2) {
        for (int idx = tid; idx < 2 * N_POINTS * STEPS; idx += 1024) {  // V copy
            int row = idx / STEPS, s = idx - row * STEPS;
            int p = row >> 1, d = row & 1;
            ((d ? g_Vy : g_Vx) + p * PAD_S)[s] = v0[idx];
        }
    } else {
        for (int p = tid; p < N_PAIRS; p += 1024) {       // pair -> row LUT
            float disc = (float)(255 * 255 - 8 * p);
            int i = (int)((255.0f - sqrtf(disc)) * 0.5f);
            i = min(max(i, 0), N_POINTS - 2);
            while (i < N_POINTS - 2 && tri_base(i + 1) <= p) ++i;
            while (i > 0 && tri_base(i) > p) --i;
            g_rowi[p] = (unsigned char)i;
        }
    }
#if __CUDA_ARCH__ >= 900
    cudaTriggerProgrammaticLaunchCompletion();
#endif
}

// ---------------------------------------------------------------------------
// Kernel B: one (pair, 2-step group) per thread; exp-free erf (4 MUFU/term).
// ---------------------------------------------------------------------------
union F4 { float4 v; float a[4]; };

__global__ void __launch_bounds__(MAIN_THREADS)
main_kernel(const float* __restrict__ data,
            const float* __restrict__ beta,
            float* __restrict__ out) {
    const int   gid = blockIdx.x * MAIN_THREADS + threadIdx.x;
    const float b0  = __ldg(&beta[0]);
#if __CUDA_ARCH__ >= 900
    cudaGridDependencySynchronize();                      // wait: prep tables visible
#endif
    float facc = 0.0f;

    if (gid < PAIR_THREADS) {
        int p  = gid / N_GROUPS;
        int s0 = (gid - p * N_GROUPS) * 2;
        int i  = (int)__ldg(&g_rowi[p]);
        int j  = i + 1 + (p - tri_base(i));

        const int oi = i * PAD_S + s0, oj = j * PAD_S + s0;
        float2 zxi = __ldg((const float2*)(g_Zx + oi));
        float2 zyi = __ldg((const float2*)(g_Zy + oi));
        float2 zxj = __ldg((const float2*)(g_Zx + oj));
        float2 zyj = __ldg((const float2*)(g_Zy + oj));
        float2 vxi = __ldg((const float2*)(g_Vx + oi));
        float2 vyi = __ldg((const float2*)(g_Vy + oi));
        float2 vxj = __ldg((const float2*)(g_Vx + oj));
        float2 vyj = __ldg((const float2*)(g_Vy + oj));
        F4 tt; tt.v = __ldg((const float4*)(&g_tstf[s0]));    // (ts0,tf0,ts1,tf1)

        #pragma unroll
        for (int k = 0; k < 2; ++k) {
            float dzx = (k ? zxi.y : zxi.x) - (k ? zxj.y : zxj.x);
            float dzy = (k ? zyi.y : zyi.x) - (k ? zyj.y : zyj.x);
            float dvx = (k ? vxi.y : vxi.x) - (k ? vxj.y : vxj.x);
            float dvy = (k ? vyi.y : vyi.x) - (k ? vyj.y : vyj.x);

            float a  = fmaxf(dvx * dvx + dvy * dvy, 1e-10f);
            float b  = 2.0f * (dzx * dvx + dzy * dvy);
            float c  = dzx * dzx + dzy * dzy;
            float bc = b0 - c;
            float ts = tt.a[2 * k];
            float tf = tt.a[2 * k + 1];

            // MUFU-free skip tests (exact algebra, see R11)
            float u = fmaf(2.0f * a, ts, b);
            float v = fmaf(2.0f * a, tf, b);
            bool live = (fmaf(4.0f * a, bc + 25.0f, b * b) > 0.0f)
                     && (u <= 0.0f || u * u < 100.0f * a)
                     && (v >= 0.0f || v * v < 100.0f * a);
            if (live) {
                float rsa    = rsqrtf(a);
                float inv2sa = 0.5f * rsa;
                float sa     = a * rsa;
                float shift  = b * inv2sa;
                float arg    = bc + shift * shift;
                float loa    = fmaf(sa, ts, shift);
                float hia    = fmaf(sa, tf, shift);
                float pref   = SQRT_PI_F * inv2sa * __expf(arg);
                facc -= pref * (fast_erf28(hia) - fast_erf28(loa));
            }
        }
    } else if (gid - PAIR_THREADS < N_EVENTS) {
        int e = gid - PAIR_THREADS;
        const float denom = DT + DT * 0.001f;
        float si = __ldg(&data[e * 3]);
        float dj = __ldg(&data[e * 3 + 1]);
        float t  = __ldg(&data[e * 3 + 2]);
        int ii = (int)si, jj = (int)dj;
        float stepf = floorf(t / denom);
        int   id    = (int)stepf;
        float delta = t - stepf * DT;
        int oi = ii * PAD_S + id, oj = jj * PAD_S + id;
        float dx = (__ldg(&g_Zx[oi]) + __ldg(&g_Vx[oi]) * delta)
                 - (__ldg(&g_Zx[oj]) + __ldg(&g_Vx[oj]) * delta);
        float dy = (__ldg(&g_Zy[oi]) + __ldg(&g_Vy[oi]) * delta)
                 - (__ldg(&g_Zy[oj]) + __ldg(&g_Vy[oj]) * delta);
        facc += b0 - (dx * dx + dy * dy);
    }

    // ---- reduction: FLOAT warp shuffle -> double smem -> warp0 -> atomic ----
    __shared__ double sRd[MAIN_THREADS / 32];
    float fv = facc;
    #pragma unroll
    for (int off = 16; off > 0; off >>= 1)                // FP32 pipe
        fv += __shfl_down_sync(0xffffffffu, fv, off);
    int warp = threadIdx.x >> 5, lane = threadIdx.x & 31;
    if (lane == 0) sRd[warp] = (double)fv;                // promote once per warp
    __syncthreads();
    if (warp == 0) {
        double v = (lane < MAIN_THREADS / 32) ? sRd[lane] : 0.0;
        #pragma unroll
        for (int off = 4; off > 0; off >>= 1)             // 3 DADD levels, warp0 only
            v += __shfl_down_sync(0xffffffffu, v, off);
        if (lane == 0) {
            atomicAdd(&g_acc, v);
            __threadfence();
            unsigned int old = atomicAdd(&g_count, 1u);
            if (old == gridDim.x - 1) {                   // last block: write + reset
                double total = atomicAdd(&g_acc, 0.0);
                out[0] = (float)total;
                g_acc   = 0.0;
                g_count = 0u;
            }
        }
    }
}

// Inputs (metadata order): data[30000], t0[1], tn[1], beta[1], z0[256], v0[12800]
extern "C" void kernel_launch(void* const* d_in, const int* in_sizes, int n_in,
                              void* d_out, int out_size) {
    const float* data = (const float*)d_in[0];
    const float* beta = (const float*)d_in[3];
    const float* z0   = (const float*)d_in[4];
    const float* v0   = (const float*)d_in[5];
    float* out = (float*)d_out;

    prep_kernel<<<4, 1024>>>(data, z0, v0);

    // PDL: overlap main's launch/dispatch with prep's execution
    cudaLaunchConfig_t cfg = {};
    cfg.gridDim  = dim3(MAIN_BLOCKS, 1, 1);
    cfg.blockDim = dim3(MAIN_THREADS, 1, 1);
    cfg.stream   = 0;
    cudaLaunchAttribute attr[1];
    attr[0].id = cudaLaunchAttributeProgrammaticStreamSerialization;
    attr[0].val.programmaticStreamSerializationAllowed = 1;
    cfg.attrs    = attr;
    cfg.numAttrs = 1;
    cudaLaunchKernelEx(&cfg, main_kernel, data, beta, out);
}